// round 6
// baseline (speedup 1.0000x reference)
#include <cuda_runtime.h>
#include <cuda_bf16.h>
#include <stdint.h>
#include <math.h>

#define BSZ 512
#define TIN 128
#define FDIM 64
#define UNITS 1024
#define OUT_STEPS 32
#define NSTEPS 159           // TIN + OUT_STEPS - 1 LSTM steps
#define NGATE 4096           // 4*UNITS, gate-interleaved: n' = u*4 + g
#define KTOT 1088            // 1024 (h) + 64 (x)
#define KCHUNK 64
#define NCHUNK 17            // 16 h-chunks + 1 x-chunk

// ---------------- persistent device scratch (allocation-free) ----------------
__device__ __nv_bfloat16 g_Wt_hi[(size_t)NGATE * KTOT];  // [n'][k], K-major
__device__ __nv_bfloat16 g_Wt_lo[(size_t)NGATE * KTOT];
__device__ float         g_b2[NGATE];                    // bias reordered to n'
__device__ __nv_bfloat16 g_in_hi[(size_t)BSZ * TIN * FDIM];
__device__ __nv_bfloat16 g_in_lo[(size_t)BSZ * TIN * FDIM];
__device__ __nv_bfloat16 g_hA_hi[(size_t)BSZ * UNITS];
__device__ __nv_bfloat16 g_hA_lo[(size_t)BSZ * UNITS];
__device__ __nv_bfloat16 g_hB_hi[(size_t)BSZ * UNITS];
__device__ __nv_bfloat16 g_hB_lo[(size_t)BSZ * UNITS];
__device__ float         g_c[(size_t)BSZ * UNITS];
__device__ __nv_bfloat16 g_xd_hi[(size_t)BSZ * FDIM];
__device__ __nv_bfloat16 g_xd_lo[(size_t)BSZ * FDIM];
__device__ int           g_flags[8][32];   // [batch lane][unit group] = steps completed
__device__ int           g_dense_flag;     // 64 * (#denses completed)

__device__ __forceinline__ uint32_t smem_u32(const void* p) {
    uint32_t a;
    asm("{ .reg .u64 t; cvta.to.shared.u64 t, %1; cvt.u32.u64 %0, t; }" : "=r"(a) : "l"(p));
    return a;
}
__device__ __forceinline__ void cp16(uint32_t saddr, const void* g) {
    asm volatile("cp.async.cg.shared.global [%0], [%1], 16;" :: "r"(saddr), "l"(g));
}
__device__ __forceinline__ void cp_commit() {
    asm volatile("cp.async.commit_group;" ::: "memory");
}
template <int N>
__device__ __forceinline__ void cp_wait() {
    asm volatile("cp.async.wait_group %0;" :: "n"(N) : "memory");
}
__device__ __forceinline__ void ldm4(uint32_t* r, uint32_t addr) {
    asm volatile("ldmatrix.sync.aligned.m8n8.x4.shared.b16 {%0,%1,%2,%3}, [%4];"
        : "=r"(r[0]), "=r"(r[1]), "=r"(r[2]), "=r"(r[3]) : "r"(addr));
}
__device__ __forceinline__ void mma16816(float* d, const uint32_t* a, const uint32_t* b) {
    asm volatile(
        "mma.sync.aligned.m16n8k16.row.col.f32.bf16.bf16.f32 "
        "{%0,%1,%2,%3}, {%4,%5,%6,%7}, {%8,%9}, {%0,%1,%2,%3};"
        : "+f"(d[0]), "+f"(d[1]), "+f"(d[2]), "+f"(d[3])
        : "r"(a[0]), "r"(a[1]), "r"(a[2]), "r"(a[3]), "r"(b[0]), "r"(b[1]));
}
__device__ __forceinline__ float sigm(float x) {
    return __fdividef(1.0f, 1.0f + __expf(-x));
}
__device__ __forceinline__ float ftanh(float x) {
    return __fdividef(2.0f, 1.0f + __expf(-2.0f * x)) - 1.0f;
}
__device__ __forceinline__ void unp2(unsigned v, float& x, float& y) {
    x = __uint_as_float(v << 16);
    y = __uint_as_float(v & 0xFFFF0000u);
}
__device__ __forceinline__ void spin_ge(const int* p, int v) {
    volatile const int* vp = (volatile const int*)p;
    if (*vp >= v) return;
    while (*vp < v) __nanosleep(64);
}

#define SWZ(o) ((o) ^ (((o) >> 3) & 0x70))

// ---------------- SMEM layout ----------------
// [0,512): bias (128 floats).
// Stage (48 KB): Ah(64x128B)=8K @0, Al @8192, Bh(128x128B)=16K @16384, Bl @32768.
// Two stages. z scratch (64x132 f32) lives in stage 1 (chunk i stage = i&1; last chunk i=16 -> stage 0).
#define A_TILE_B 8192
#define B_TILE_B 16384
#define STAGE_B 49152
#define SM_STG 512
#define SM_TOTAL (SM_STG + 2 * STAGE_B)   // 98816

__global__ __launch_bounds__(256, 2)
void lstm_persist(const float* __restrict__ Wd,
                  const float* __restrict__ bd,
                  float* __restrict__ out)
{
    extern __shared__ char smem[];
    const uint32_t sbase = smem_u32(smem);
    const int tid = threadIdx.x, wid = tid >> 5, lane = tid & 31;
    const int warp_m = wid >> 2;            // 0..1 -> rows warp_m*32
    const int warp_n = wid & 3;             // 0..3 -> cols warp_n*32
    const int bx = blockIdx.x;              // batch lane 0..7
    const int by = blockIdx.y;              // unit group 0..31
    const int m0 = bx * 64;
    const int n0 = by * 128;
    const int u0 = by * 32;
    const int flat = by * gridDim.x + bx;

    if (tid < 128) ((float*)smem)[tid] = g_b2[n0 + tid];

    const __nv_bfloat16* __restrict__ Bh = g_Wt_hi + (size_t)n0 * KTOT;
    const __nv_bfloat16* __restrict__ Bl = g_Wt_lo + (size_t)n0 * KTOT;

    const int a_r  = warp_m * 32 + (lane & 15);
    const int a_cs = (lane >> 4) * 16;
    const int b_r  = warp_n * 32 + (lane & 7) + ((lane >> 4) << 3);
    const int b_cs = ((lane >> 3) & 1) * 16;

    auto issueW = [&](int c, int st) {
        const uint32_t sb = sbase + SM_STG + st * STAGE_B + 2 * A_TILE_B;
        #pragma unroll
        for (int i = 0; i < 4; ++i) {
            const int idx = i * 256 + tid;
            const int row = idx >> 3, ch = idx & 7;
            const uint32_t so = SWZ(row * 128 + ch * 16);
            const size_t go = (size_t)row * KTOT + c * KCHUNK + ch * 8;
            cp16(sb + so,            Bh + go);
            cp16(sb + B_TILE_B + so, Bl + go);
        }
    };

    #pragma unroll 1
    for (int t = 0; t < NSTEPS; ++t) {
        const __nv_bfloat16* hih = (t & 1) ? g_hB_hi : g_hA_hi;
        const __nv_bfloat16* hil = (t & 1) ? g_hB_lo : g_hA_lo;
        __nv_bfloat16* hoh = (t & 1) ? g_hA_hi : g_hB_hi;
        __nv_bfloat16* hol = (t & 1) ? g_hA_lo : g_hB_lo;
        const __nv_bfloat16 *xh, *xl;
        int xstride;
        const bool warm = (t < TIN);
        if (warm) { xh = g_in_hi + (size_t)t * FDIM; xl = g_in_lo + (size_t)t * FDIM; xstride = TIN * FDIM; }
        else      { xh = g_xd_hi; xl = g_xd_lo; xstride = FDIM; }

        // chunk order: warm-up -> x first (no dependency); decode -> x last
        const int nchunks = (t == 0) ? 1 : NCHUNK;
        auto cmap = [&](int i) -> int { return warm ? ((i == 0) ? 16 : i - 1) : i; };

        auto waitflags = [&](int c) {
            if (c < 16) {
                if (t > 0) {
                    spin_ge(&g_flags[bx][2 * c], t);
                    spin_ge(&g_flags[bx][2 * c + 1], t);
                    __threadfence();
                }
            } else if (!warm) {
                spin_ge(&g_dense_flag, 64 * (t - TIN + 1));
                __threadfence();
            }
        };

        auto issueA = [&](int c, int st) {
            const __nv_bfloat16 *ah, *al;
            int lda;
            if (c < 16) {
                ah = hih + (size_t)m0 * UNITS + c * KCHUNK;
                al = hil + (size_t)m0 * UNITS + c * KCHUNK;
                lda = UNITS;
            } else {
                ah = xh + (size_t)m0 * xstride;
                al = xl + (size_t)m0 * xstride;
                lda = xstride;
            }
            const uint32_t sb = sbase + SM_STG + st * STAGE_B;
            #pragma unroll
            for (int i = 0; i < 2; ++i) {
                const int idx = i * 256 + tid;
                const int row = idx >> 3, ch = idx & 7;
                const uint32_t so = SWZ(row * 128 + ch * 16);
                cp16(sb + so,            ah + (size_t)row * lda + ch * 8);
                cp16(sb + A_TILE_B + so, al + (size_t)row * lda + ch * 8);
            }
        };

        // prologue: chunk cmap(0) into stage 0
        {
            const int c = cmap(0);
            issueW(c, 0);
            waitflags(c);
            issueA(c, 0);
            cp_commit();
        }

        float acc[2][4][4];
        #pragma unroll
        for (int i = 0; i < 2; ++i)
            #pragma unroll
            for (int j = 0; j < 4; ++j)
                #pragma unroll
                for (int r = 0; r < 4; ++r) acc[i][j][r] = 0.f;

        #pragma unroll 1
        for (int i = 0; i < nchunks; ++i) {
            const int st = i & 1;
            cp_wait<0>();
            __syncthreads();
            if (i + 1 < nchunks) {
                const int cn = cmap(i + 1);
                issueW(cn, st ^ 1);
                waitflags(cn);
                issueA(cn, st ^ 1);
                cp_commit();
            }

            const uint32_t sb = sbase + SM_STG + st * STAGE_B;
            #pragma unroll
            for (int k16 = 0; k16 < 4; ++k16) {
                const int kb = k16 * 32;
                uint32_t ah[2][4], al[2][4], bh[2][4], bl[2][4];
                #pragma unroll
                for (int mf = 0; mf < 2; ++mf) {
                    const uint32_t so = SWZ((a_r + mf * 16) * 128 + kb + a_cs);
                    ldm4(ah[mf], sb + so);
                    ldm4(al[mf], sb + A_TILE_B + so);
                }
                #pragma unroll
                for (int p = 0; p < 2; ++p) {
                    const uint32_t so = SWZ((b_r + p * 16) * 128 + kb + b_cs);
                    ldm4(bh[p], sb + 2 * A_TILE_B + so);
                    ldm4(bl[p], sb + 2 * A_TILE_B + B_TILE_B + so);
                }
                #pragma unroll
                for (int mf = 0; mf < 2; ++mf)
                    #pragma unroll
                    for (int nf = 0; nf < 4; ++nf)
                        mma16816(acc[mf][nf], ah[mf], &bh[nf >> 1][(nf & 1) * 2]);
                #pragma unroll
                for (int mf = 0; mf < 2; ++mf)
                    #pragma unroll
                    for (int nf = 0; nf < 4; ++nf)
                        mma16816(acc[mf][nf], ah[mf], &bl[nf >> 1][(nf & 1) * 2]);
                #pragma unroll
                for (int mf = 0; mf < 2; ++mf)
                    #pragma unroll
                    for (int nf = 0; nf < 4; ++nf)
                        mma16816(acc[mf][nf], al[mf], &bh[nf >> 1][(nf & 1) * 2]);
            }
        }

        // ---- epilogue: z scratch in stage 1 (last chunk computed from stage 0) ----
        float* zs = (float*)(smem + SM_STG + STAGE_B);
        __syncthreads();
        {
            const int gr = lane >> 2, gcn = (lane & 3) * 2;
            #pragma unroll
            for (int mf = 0; mf < 2; ++mf)
                #pragma unroll
                for (int nf = 0; nf < 4; ++nf) {
                    const int row = warp_m * 32 + mf * 16 + gr;
                    const int col = warp_n * 32 + nf * 8 + gcn;
                    *(float2*)&zs[row * 132 + col]       = make_float2(acc[mf][nf][0], acc[mf][nf][1]);
                    *(float2*)&zs[(row + 8) * 132 + col] = make_float2(acc[mf][nf][2], acc[mf][nf][3]);
                }
        }
        __syncthreads();
        {
            const int m  = tid >> 2;
            const int ub = (tid & 3) * 8;
            const float4* zrow  = (const float4*)&zs[m * 132];
            const float4* bias4 = (const float4*)smem;
            const size_t idx0 = (size_t)(m0 + m) * UNITS + u0 + ub;
            __align__(16) float cf[8];
            __align__(16) __nv_bfloat16 hh[8], hl[8];
            if (t == 0) {
                #pragma unroll
                for (int j = 0; j < 8; ++j) cf[j] = 0.f;
            } else {
                *(float4*)&cf[0] = *(const float4*)(g_c + idx0);
                *(float4*)&cf[4] = *(const float4*)(g_c + idx0 + 4);
            }
            #pragma unroll
            for (int j = 0; j < 8; ++j) {
                const int ul = ub + j;
                const float4 z4 = zrow[ul];
                const float4 bb = bias4[ul];
                const float zi = z4.x + bb.x;
                const float zf = z4.y + bb.y;
                const float zg = z4.z + bb.z;
                const float zo = z4.w + bb.w;
                const float cn = sigm(zf) * cf[j] + sigm(zi) * ftanh(zg);
                cf[j] = cn;
                const float h = sigm(zo) * ftanh(cn);
                const __nv_bfloat16 hhi = __float2bfloat16(h);
                hh[j] = hhi;
                hl[j] = __float2bfloat16(h - __bfloat162float(hhi));
            }
            *(float4*)(g_c + idx0)     = *(const float4*)&cf[0];
            *(float4*)(g_c + idx0 + 4) = *(const float4*)&cf[4];
            *(uint4*)(hoh + idx0) = *(const uint4*)&hh[0];
            *(uint4*)(hol + idx0) = *(const uint4*)&hl[0];
        }

        // release: h(t+1) for this (lane, group) is visible
        __threadfence();
        __syncthreads();
        if (tid == 0) atomicExch(&g_flags[bx][by], t + 1);

        // dense head (assigned to late-consumed groups by=24..31)
        if (t >= TIN - 1 && flat >= 192) {
            const int flat2 = flat - 192;
            const int bg = flat2 >> 3;
            const int fg = flat2 & 7;
            const int ds = t - (TIN - 1);
            if (tid < 32) spin_ge(&g_flags[bg][tid], t + 1);
            __syncthreads();
            __threadfence();
            const __nv_bfloat16* dh = hoh;
            const __nv_bfloat16* dl = hol;
            const int bl_ = tid >> 2;
            const int f0 = fg * 8 + (tid & 3);
            const int b  = bg * 64 + bl_;
            const uint2* hhp = (const uint2*)(dh + (size_t)b * UNITS);
            const uint2* hlp = (const uint2*)(dl + (size_t)b * UNITS);
            float a0 = 0.f, a1 = 0.f;
            #pragma unroll 4
            for (int kq = 0; kq < UNITS / 4; ++kq) {
                const uint2 vh = __ldcg(hhp + kq);
                const uint2 vl = __ldcg(hlp + kq);
                float h0, h1, h2, h3, l0, l1, l2, l3;
                unp2(vh.x, h0, h1); unp2(vh.y, h2, h3);
                unp2(vl.x, l0, l1); unp2(vl.y, l2, l3);
                const float hv0 = h0 + l0, hv1 = h1 + l1, hv2 = h2 + l2, hv3 = h3 + l3;
                const float* w = Wd + (size_t)kq * 4 * FDIM;
                a0 = fmaf(hv0, w[f0], a0);            a1 = fmaf(hv0, w[f0 + 4], a1);
                a0 = fmaf(hv1, w[64 + f0], a0);       a1 = fmaf(hv1, w[64 + f0 + 4], a1);
                a0 = fmaf(hv2, w[128 + f0], a0);      a1 = fmaf(hv2, w[128 + f0 + 4], a1);
                a0 = fmaf(hv3, w[192 + f0], a0);      a1 = fmaf(hv3, w[192 + f0 + 4], a1);
            }
            const float p0 = a0 + bd[f0];
            const float p1 = a1 + bd[f0 + 4];
            out[(size_t)b * (OUT_STEPS * FDIM) + (size_t)ds * FDIM + f0]     = p0;
            out[(size_t)b * (OUT_STEPS * FDIM) + (size_t)ds * FDIM + f0 + 4] = p1;
            const __nv_bfloat16 p0h = __float2bfloat16(p0);
            const __nv_bfloat16 p1h = __float2bfloat16(p1);
            g_xd_hi[(size_t)b * FDIM + f0]     = p0h;
            g_xd_hi[(size_t)b * FDIM + f0 + 4] = p1h;
            g_xd_lo[(size_t)b * FDIM + f0]     = __float2bfloat16(p0 - __bfloat162float(p0h));
            g_xd_lo[(size_t)b * FDIM + f0 + 4] = __float2bfloat16(p1 - __bfloat162float(p1h));
            __threadfence();
            __syncthreads();
            if (tid == 0) atomicAdd(&g_dense_flag, 1);
        }
    }
}

// ---------------- preprocessing: coalesced tiled transpose ----------------
__global__ __launch_bounds__(256)
void prep_weights(const float* __restrict__ Wk, const float* __restrict__ Wr,
                  const float* __restrict__ b) {
    __shared__ float tile[64][65];            // [n'_loc][k_loc]
    const int k0 = blockIdx.x * 64;
    const int u0 = blockIdx.y * 16;
    const int r  = threadIdx.x >> 2;
    const int cq = threadIdx.x & 3;
    const int k  = k0 + r;
    #pragma unroll
    for (int g = 0; g < 4; ++g) {
        const int col = g * UNITS + u0 + cq * 4;
        float4 v;
        if (k < UNITS) v = *(const float4*)(Wr + (size_t)k * NGATE + col);
        else           v = *(const float4*)(Wk + (size_t)(k - UNITS) * NGATE + col);
        tile[(cq * 4 + 0) * 4 + g][r] = v.x;
        tile[(cq * 4 + 1) * 4 + g][r] = v.y;
        tile[(cq * 4 + 2) * 4 + g][r] = v.z;
        tile[(cq * 4 + 3) * 4 + g][r] = v.w;
    }
    if (blockIdx.x == 0 && blockIdx.y == 0)
        for (int i = threadIdx.x; i < NGATE; i += 256)
            g_b2[i] = b[(i & 3) * UNITS + (i >> 2)];
    __syncthreads();
    const int nl = threadIdx.x >> 2;
    const int kk = (threadIdx.x & 3) * 16;
    const size_t ng = (size_t)(blockIdx.y * 64 + nl);
    __align__(16) __nv_bfloat16 hb[16], lb[16];
    #pragma unroll
    for (int j = 0; j < 16; ++j) {
        const float v = tile[nl][kk + j];
        const __nv_bfloat16 hi = __float2bfloat16(v);
        hb[j] = hi;
        lb[j] = __float2bfloat16(v - __bfloat162float(hi));
    }
    *(uint4*)(g_Wt_hi + ng * KTOT + k0 + kk)     = *(const uint4*)&hb[0];
    *(uint4*)(g_Wt_hi + ng * KTOT + k0 + kk + 8) = *(const uint4*)&hb[8];
    *(uint4*)(g_Wt_lo + ng * KTOT + k0 + kk)     = *(const uint4*)&lb[0];
    *(uint4*)(g_Wt_lo + ng * KTOT + k0 + kk + 8) = *(const uint4*)&lb[8];
}

__global__ void prep_inputs(const float* __restrict__ inp) {
    const size_t idx = (size_t)blockIdx.x * blockDim.x + threadIdx.x;
    if (idx < (size_t)BSZ * TIN * FDIM) {
        const float v = inp[idx];
        const __nv_bfloat16 hi = __float2bfloat16(v);
        g_in_hi[idx] = hi;
        g_in_lo[idx] = __float2bfloat16(v - __bfloat162float(hi));
    }
}

// ---------------- launch ----------------
extern "C" void kernel_launch(void* const* d_in, const int* in_sizes, int n_in,
                              void* d_out, int out_size)
{
    const float* inputs = (const float*)d_in[0];
    const float* Wk     = (const float*)d_in[1];
    const float* Wr     = (const float*)d_in[2];
    const float* bias   = (const float*)d_in[3];
    const float* Wd     = (const float*)d_in[4];
    const float* bd     = (const float*)d_in[5];
    float* out = (float*)d_out;

    static bool attr_done = false;
    if (!attr_done) {
        cudaFuncSetAttribute(lstm_persist, cudaFuncAttributeMaxDynamicSharedMemorySize, SM_TOTAL);
        attr_done = true;
    }

    void* flags_addr;
    void* dflag_addr;
    cudaGetSymbolAddress(&flags_addr, g_flags);
    cudaGetSymbolAddress(&dflag_addr, g_dense_flag);
    cudaMemsetAsync(flags_addr, 0, 8 * 32 * sizeof(int));
    cudaMemsetAsync(dflag_addr, 0, sizeof(int));

    prep_weights<<<dim3(17, 64), 256>>>(Wk, Wr, bias);
    {
        const size_t ni = (size_t)BSZ * TIN * FDIM;
        prep_inputs<<<(unsigned)((ni + 255) / 256), 256>>>(inputs);
    }

    lstm_persist<<<dim3(BSZ / 64, NGATE / 128), 256, SM_TOTAL>>>(Wd, bd, out);
}

// round 7
// speedup vs baseline: 1.5900x; 1.5900x over previous
#include <cuda_runtime.h>
#include <cuda_fp16.h>
#include <stdint.h>
#include <math.h>

#define BSZ 512
#define TIN 128
#define FDIM 64
#define UNITS 1024
#define OUT_STEPS 32
#define NSTEPS 159           // TIN + OUT_STEPS - 1 LSTM steps
#define NGATE 4096           // 4*UNITS, gate-interleaved: n' = u*4 + g
#define KTOT 1088            // 1024 (h) + 64 (x)
#define KCHUNK 64
#define NCHUNK 17            // 16 h-chunks + 1 x-chunk
#define NBLK 256

// ---------------- persistent device scratch (allocation-free) ----------------
__device__ __half g_Wt[(size_t)NGATE * KTOT];     // fp16 weights, [n'][k] K-major
__device__ float  g_b2[NGATE];                    // bias reordered to n'
__device__ __half g_in_hi[(size_t)BSZ * TIN * FDIM];
__device__ __half g_in_lo[(size_t)BSZ * TIN * FDIM];
__device__ __half g_hA_hi[(size_t)BSZ * UNITS];
__device__ __half g_hA_lo[(size_t)BSZ * UNITS];
__device__ __half g_hB_hi[(size_t)BSZ * UNITS];
__device__ __half g_hB_lo[(size_t)BSZ * UNITS];
__device__ float  g_c[(size_t)BSZ * UNITS];
__device__ __half g_xd_hi[(size_t)BSZ * FDIM];
__device__ __half g_xd_lo[(size_t)BSZ * FDIM];
__device__ unsigned g_bar[2];                     // [0]=count, [1]=generation

__device__ __forceinline__ uint32_t smem_u32(const void* p) {
    uint32_t a;
    asm("{ .reg .u64 t; cvta.to.shared.u64 t, %1; cvt.u32.u64 %0, t; }" : "=r"(a) : "l"(p));
    return a;
}
__device__ __forceinline__ void cp16(uint32_t saddr, const void* g) {
    asm volatile("cp.async.cg.shared.global [%0], [%1], 16;" :: "r"(saddr), "l"(g));
}
__device__ __forceinline__ void cp_commit() {
    asm volatile("cp.async.commit_group;" ::: "memory");
}
template <int N>
__device__ __forceinline__ void cp_wait() {
    asm volatile("cp.async.wait_group %0;" :: "n"(N) : "memory");
}
__device__ __forceinline__ void ldm4(uint32_t* r, uint32_t addr) {
    asm volatile("ldmatrix.sync.aligned.m8n8.x4.shared.b16 {%0,%1,%2,%3}, [%4];"
        : "=r"(r[0]), "=r"(r[1]), "=r"(r[2]), "=r"(r[3]) : "r"(addr));
}
// mma.sync m16n8k16 row.col fp16 -> f32 (baseline PTX)
__device__ __forceinline__ void mma16816(float* d, const uint32_t* a, const uint32_t* b) {
    asm volatile(
        "mma.sync.aligned.m16n8k16.row.col.f32.f16.f16.f32 "
        "{%0,%1,%2,%3}, {%4,%5,%6,%7}, {%8,%9}, {%0,%1,%2,%3};"
        : "+f"(d[0]), "+f"(d[1]), "+f"(d[2]), "+f"(d[3])
        : "r"(a[0]), "r"(a[1]), "r"(a[2]), "r"(a[3]), "r"(b[0]), "r"(b[1]));
}
__device__ __forceinline__ float sigm(float x) {
    return __fdividef(1.0f, 1.0f + __expf(-x));
}
__device__ __forceinline__ float ftanh(float x) {
    return __fdividef(2.0f, 1.0f + __expf(-2.0f * x)) - 1.0f;
}
__device__ __forceinline__ void unph(unsigned v, float& x, float& y) {
    const __half2 p = *reinterpret_cast<const __half2*>(&v);
    const float2 f = __half22float2(p);
    x = f.x; y = f.y;
}

#define SWZ(o) ((o) ^ (((o) >> 3) & 0x70))

// ---------------- SMEM layout ----------------
// [0,512): bias (128 floats).
// Stage (32 KB): Ah(64x128B)=8K @0, Al @8192, Bh(128x128B)=16K @16384.
// Two stages. z scratch (64x132 f32 = 33792 B) at SM_STG+STAGE_B (last chunk uses stage 0).
#define A_TILE_B 8192
#define B_TILE_B 16384
#define STAGE_B 32768
#define SM_STG 512
#define SM_TOTAL (SM_STG + STAGE_B + 33792)   // 67072

__device__ __forceinline__ void grid_barrier(unsigned target) {
    __threadfence();
    __syncthreads();
    if (threadIdx.x == 0) {
        if (atomicAdd(&g_bar[0], 1u) == NBLK - 1u) {
            atomicExch(&g_bar[0], 0u);
            __threadfence();
            atomicExch(&g_bar[1], target);
        } else {
            while (((volatile unsigned*)g_bar)[1] < target) __nanosleep(64);
            __threadfence();
        }
    }
    __syncthreads();
}

__global__ __launch_bounds__(256, 2)
void lstm_persist(const float* __restrict__ Wd,
                  const float* __restrict__ bd,
                  float* __restrict__ out)
{
    extern __shared__ char smem[];
    const uint32_t sbase = smem_u32(smem);
    const int tid = threadIdx.x, wid = tid >> 5, lane = tid & 31;
    const int warp_m = wid >> 2;            // 0..1 -> rows warp_m*32
    const int warp_n = wid & 3;             // 0..3 -> cols warp_n*32
    const int m0 = blockIdx.x * 64;         // batch tile (M=64)
    const int n0 = blockIdx.y * 128;        // gate-interleaved column base (N=128)
    const int u0 = blockIdx.y * 32;
    const int flat = blockIdx.y * gridDim.x + blockIdx.x;

    if (tid < 128) ((float*)smem)[tid] = g_b2[n0 + tid];

    const __half* __restrict__ Bw = g_Wt + (size_t)n0 * KTOT;

    const int a_r  = warp_m * 32 + (lane & 15);
    const int a_cs = (lane >> 4) * 16;
    const int b_r  = warp_n * 32 + (lane & 7) + ((lane >> 4) << 3);
    const int b_cs = ((lane >> 3) & 1) * 16;

    unsigned lgen = 0;

    // W loader (weights are step-invariant)
    auto issueW = [&](int c, int st) {
        const uint32_t sb = sbase + SM_STG + st * STAGE_B + 2 * A_TILE_B;
        #pragma unroll
        for (int i = 0; i < 4; ++i) {
            const int idx = i * 256 + tid;
            const int row = idx >> 3, ch = idx & 7;
            const uint32_t so = SWZ(row * 128 + ch * 16);
            cp16(sb + so, Bw + (size_t)row * KTOT + c * KCHUNK + ch * 8);
        }
    };

    #pragma unroll 1
    for (int t = 0; t < NSTEPS; ++t) {
        const __half* hih = (t & 1) ? g_hB_hi : g_hA_hi;
        const __half* hil = (t & 1) ? g_hB_lo : g_hA_lo;
        __half* hoh = (t & 1) ? g_hA_hi : g_hB_hi;
        __half* hol = (t & 1) ? g_hA_lo : g_hB_lo;
        const __half *xh, *xl;
        int xstride;
        if (t < TIN) { xh = g_in_hi + (size_t)t * FDIM; xl = g_in_lo + (size_t)t * FDIM; xstride = TIN * FDIM; }
        else         { xh = g_xd_hi; xl = g_xd_lo; xstride = FDIM; }

        auto issueA = [&](int c, int st) {
            const __half *ah, *al;
            int lda;
            if (c < 16) {
                ah = hih + (size_t)m0 * UNITS + c * KCHUNK;
                al = hil + (size_t)m0 * UNITS + c * KCHUNK;
                lda = UNITS;
            } else {
                ah = xh + (size_t)m0 * xstride;
                al = xl + (size_t)m0 * xstride;
                lda = xstride;
            }
            const uint32_t sb = sbase + SM_STG + st * STAGE_B;
            #pragma unroll
            for (int i = 0; i < 2; ++i) {
                const int idx = i * 256 + tid;
                const int row = idx >> 3, ch = idx & 7;
                const uint32_t so = SWZ(row * 128 + ch * 16);
                cp16(sb + so,            ah + (size_t)row * lda + ch * 8);
                cp16(sb + A_TILE_B + so, al + (size_t)row * lda + ch * 8);
            }
        };

        int c0;
        if (t == 0) { c0 = 16; issueA(16, 0); issueW(16, 0); cp_commit(); }
        else        { c0 = 0;  issueA(0, 0);  cp_commit(); }   // W0 pre-issued last step

        float acc[2][4][4];
        #pragma unroll
        for (int i = 0; i < 2; ++i)
            #pragma unroll
            for (int j = 0; j < 4; ++j)
                #pragma unroll
                for (int r = 0; r < 4; ++r) acc[i][j][r] = 0.f;

        #pragma unroll 1
        for (int c = c0; c < NCHUNK; ++c) {
            const int st = c & 1;
            cp_wait<0>();
            __syncthreads();
            if (c + 1 < NCHUNK) { issueA(c + 1, st ^ 1); issueW(c + 1, st ^ 1); cp_commit(); }

            const uint32_t sb = sbase + SM_STG + st * STAGE_B;
            #pragma unroll
            for (int k16 = 0; k16 < 4; ++k16) {
                const int kb = k16 * 32;
                uint32_t ah[2][4], al[2][4], bh[2][4];
                #pragma unroll
                for (int mf = 0; mf < 2; ++mf) {
                    const uint32_t so = SWZ((a_r + mf * 16) * 128 + kb + a_cs);
                    ldm4(ah[mf], sb + so);
                    ldm4(al[mf], sb + A_TILE_B + so);
                }
                #pragma unroll
                for (int p = 0; p < 2; ++p) {
                    const uint32_t so = SWZ((b_r + p * 16) * 128 + kb + b_cs);
                    ldm4(bh[p], sb + 2 * A_TILE_B + so);
                }
                #pragma unroll
                for (int mf = 0; mf < 2; ++mf)
                    #pragma unroll
                    for (int nf = 0; nf < 4; ++nf)
                        mma16816(acc[mf][nf], ah[mf], &bh[nf >> 1][(nf & 1) * 2]);
                #pragma unroll
                for (int mf = 0; mf < 2; ++mf)
                    #pragma unroll
                    for (int nf = 0; nf < 4; ++nf)
                        mma16816(acc[mf][nf], al[mf], &bh[nf >> 1][(nf & 1) * 2]);
            }
        }

        // ---- epilogue: z scratch after stage 0 (last chunk c=16 computed from stage 0) ----
        float* zs = (float*)(smem + SM_STG + STAGE_B);
        __syncthreads();
        {
            const int gr = lane >> 2, gcn = (lane & 3) * 2;
            #pragma unroll
            for (int mf = 0; mf < 2; ++mf)
                #pragma unroll
                for (int nf = 0; nf < 4; ++nf) {
                    const int row = warp_m * 32 + mf * 16 + gr;
                    const int col = warp_n * 32 + nf * 8 + gcn;
                    *(float2*)&zs[row * 132 + col]       = make_float2(acc[mf][nf][0], acc[mf][nf][1]);
                    *(float2*)&zs[(row + 8) * 132 + col] = make_float2(acc[mf][nf][2], acc[mf][nf][3]);
                }
        }
        __syncthreads();
        {
            const int m  = tid >> 2;
            const int ub = (tid & 3) * 8;
            const float4* zrow  = (const float4*)&zs[m * 132];
            const float4* bias4 = (const float4*)smem;
            const size_t idx0 = (size_t)(m0 + m) * UNITS + u0 + ub;
            __align__(16) float cf[8];
            __align__(8) __half hh[8], hl[8];
            if (t == 0) {
                #pragma unroll
                for (int j = 0; j < 8; ++j) cf[j] = 0.f;
            } else {
                *(float4*)&cf[0] = *(const float4*)(g_c + idx0);
                *(float4*)&cf[4] = *(const float4*)(g_c + idx0 + 4);
            }
            #pragma unroll
            for (int j = 0; j < 8; ++j) {
                const int ul = ub + j;
                const float4 z4 = zrow[ul];
                const float4 bb = bias4[ul];
                const float zi = z4.x + bb.x;
                const float zf = z4.y + bb.y;
                const float zg = z4.z + bb.z;
                const float zo = z4.w + bb.w;
                const float cn = sigm(zf) * cf[j] + sigm(zi) * ftanh(zg);
                cf[j] = cn;
                const float h = sigm(zo) * ftanh(cn);
                const __half hhi = __float2half(h);
                hh[j] = hhi;
                hl[j] = __float2half(h - __half2float(hhi));
            }
            *(float4*)(g_c + idx0)     = *(const float4*)&cf[0];
            *(float4*)(g_c + idx0 + 4) = *(const float4*)&cf[4];
            *(uint4*)(hoh + idx0) = *(const uint4*)&hh[0];
            *(uint4*)(hol + idx0) = *(const uint4*)&hl[0];
        }

        if (t + 1 < NSTEPS) { issueW(0, 0); cp_commit(); }   // prefetch next step's W0 across the barrier
        grid_barrier(++lgen);

        if (t >= TIN - 1) {
            const int ds = t - (TIN - 1);
            if (flat < 64) {
                const int bg = flat >> 3;
                const int fg = flat & 7;
                const int bl_ = tid >> 2;
                const int f0 = fg * 8 + (tid & 3);
                const int b  = bg * 64 + bl_;
                const uint2* hhp = (const uint2*)(hoh + (size_t)b * UNITS);
                const uint2* hlp = (const uint2*)(hol + (size_t)b * UNITS);
                float a0 = 0.f, a1 = 0.f;
                #pragma unroll 4
                for (int kq = 0; kq < UNITS / 4; ++kq) {
                    const uint2 vh = __ldcg(hhp + kq);
                    const uint2 vl = __ldcg(hlp + kq);
                    float h0, h1, h2, h3, l0, l1, l2, l3;
                    unph(vh.x, h0, h1); unph(vh.y, h2, h3);
                    unph(vl.x, l0, l1); unph(vl.y, l2, l3);
                    const float hv0 = h0 + l0, hv1 = h1 + l1, hv2 = h2 + l2, hv3 = h3 + l3;
                    const float* w = Wd + (size_t)kq * 4 * FDIM;
                    a0 = fmaf(hv0, w[f0], a0);            a1 = fmaf(hv0, w[f0 + 4], a1);
                    a0 = fmaf(hv1, w[64 + f0], a0);       a1 = fmaf(hv1, w[64 + f0 + 4], a1);
                    a0 = fmaf(hv2, w[128 + f0], a0);      a1 = fmaf(hv2, w[128 + f0 + 4], a1);
                    a0 = fmaf(hv3, w[192 + f0], a0);      a1 = fmaf(hv3, w[192 + f0 + 4], a1);
                }
                const float p0 = a0 + bd[f0];
                const float p1 = a1 + bd[f0 + 4];
                out[(size_t)b * (OUT_STEPS * FDIM) + (size_t)ds * FDIM + f0]     = p0;
                out[(size_t)b * (OUT_STEPS * FDIM) + (size_t)ds * FDIM + f0 + 4] = p1;
                const __half p0h = __float2half(p0);
                const __half p1h = __float2half(p1);
                g_xd_hi[(size_t)b * FDIM + f0]     = p0h;
                g_xd_hi[(size_t)b * FDIM + f0 + 4] = p1h;
                g_xd_lo[(size_t)b * FDIM + f0]     = __float2half(p0 - __half2float(p0h));
                g_xd_lo[(size_t)b * FDIM + f0 + 4] = __float2half(p1 - __half2float(p1h));
            }
            if (t + 1 < NSTEPS) grid_barrier(++lgen);
        }
    }
}

// ---------------- preprocessing: coalesced tiled transpose to fp16 ----------------
__global__ __launch_bounds__(256)
void prep_weights(const float* __restrict__ Wk, const float* __restrict__ Wr,
                  const float* __restrict__ b) {
    __shared__ float tile[64][65];            // [n'_loc][k_loc]
    const int k0 = blockIdx.x * 64;
    const int u0 = blockIdx.y * 16;
    const int r  = threadIdx.x >> 2;
    const int cq = threadIdx.x & 3;
    const int k  = k0 + r;
    #pragma unroll
    for (int g = 0; g < 4; ++g) {
        const int col = g * UNITS + u0 + cq * 4;
        float4 v;
        if (k < UNITS) v = *(const float4*)(Wr + (size_t)k * NGATE + col);
        else           v = *(const float4*)(Wk + (size_t)(k - UNITS) * NGATE + col);
        tile[(cq * 4 + 0) * 4 + g][r] = v.x;
        tile[(cq * 4 + 1) * 4 + g][r] = v.y;
        tile[(cq * 4 + 2) * 4 + g][r] = v.z;
        tile[(cq * 4 + 3) * 4 + g][r] = v.w;
    }
    if (blockIdx.x == 0 && blockIdx.y == 0)
        for (int i = threadIdx.x; i < NGATE; i += 256)
            g_b2[i] = b[(i & 3) * UNITS + (i >> 2)];
    __syncthreads();
    const int nl = threadIdx.x >> 2;
    const int kk = (threadIdx.x & 3) * 16;
    const size_t ng = (size_t)(blockIdx.y * 64 + nl);
    __align__(16) __half hb[16];
    #pragma unroll
    for (int j = 0; j < 16; ++j)
        hb[j] = __float2half(tile[nl][kk + j]);
    *(uint4*)(g_Wt + ng * KTOT + k0 + kk)     = *(const uint4*)&hb[0];
    *(uint4*)(g_Wt + ng * KTOT + k0 + kk + 8) = *(const uint4*)&hb[8];
}

__global__ void prep_inputs(const float* __restrict__ inp) {
    const size_t idx = (size_t)blockIdx.x * blockDim.x + threadIdx.x;
    if (idx < (size_t)BSZ * TIN * FDIM) {
        const float v = inp[idx];
        const __half hi = __float2half(v);
        g_in_hi[idx] = hi;
        g_in_lo[idx] = __float2half(v - __half2float(hi));
    }
}

// ---------------- launch ----------------
extern "C" void kernel_launch(void* const* d_in, const int* in_sizes, int n_in,
                              void* d_out, int out_size)
{
    const float* inputs = (const float*)d_in[0];
    const float* Wk     = (const float*)d_in[1];
    const float* Wr     = (const float*)d_in[2];
    const float* bias   = (const float*)d_in[3];
    const float* Wd     = (const float*)d_in[4];
    const float* bd     = (const float*)d_in[5];
    float* out = (float*)d_out;

    static bool attr_done = false;
    if (!attr_done) {
        cudaFuncSetAttribute(lstm_persist, cudaFuncAttributeMaxDynamicSharedMemorySize, SM_TOTAL);
        attr_done = true;
    }

    void* bar_addr;
    cudaGetSymbolAddress(&bar_addr, g_bar);
    cudaMemsetAsync(bar_addr, 0, 2 * sizeof(unsigned));

    prep_weights<<<dim3(17, 64), 256>>>(Wk, Wr, bias);
    {
        const size_t ni = (size_t)BSZ * TIN * FDIM;
        prep_inputs<<<(unsigned)((ni + 255) / 256), 256>>>(inputs);
    }

    lstm_persist<<<dim3(BSZ / 64, NGATE / 128), 256, SM_TOTAL>>>(Wd, bd, out);
}

// round 8
// speedup vs baseline: 2.1907x; 1.3778x over previous
#include <cuda_runtime.h>
#include <cuda_fp16.h>
#include <stdint.h>
#include <math.h>

#define BSZ 512
#define TIN 128
#define FDIM 64
#define UNITS 1024
#define OUT_STEPS 32
#define NSTEPS 159           // TIN + OUT_STEPS - 1 LSTM steps
#define NGATE 4096           // 4*UNITS, gate-interleaved: n' = u*4 + g
#define KTOT 1088            // 1024 (h) + 64 (x)
#define KCHUNK 64
#define NCHUNK 17            // 16 h-chunks + 1 x-chunk
#define NBLK 256

// ---------------- persistent device scratch (allocation-free) ----------------
__device__ __half g_Wt[(size_t)NGATE * KTOT];     // fp16 weights, [n'][k] K-major
__device__ float  g_b2[NGATE];                    // bias reordered to n'
__device__ __half g_in[(size_t)BSZ * TIN * FDIM]; // fp16 inputs
__device__ __half g_hA[(size_t)BSZ * UNITS];
__device__ __half g_hB[(size_t)BSZ * UNITS];
__device__ float  g_hf32[(size_t)BSZ * UNITS];    // fp32 h (decode region only)
__device__ float  g_c[(size_t)BSZ * UNITS];
__device__ __half g_xd[(size_t)BSZ * FDIM];       // decode input = fp16(pred)
__device__ unsigned g_bar[2];                     // [0]=count, [1]=generation

__device__ __forceinline__ uint32_t smem_u32(const void* p) {
    uint32_t a;
    asm("{ .reg .u64 t; cvta.to.shared.u64 t, %1; cvt.u32.u64 %0, t; }" : "=r"(a) : "l"(p));
    return a;
}
__device__ __forceinline__ void cp16(uint32_t saddr, const void* g) {
    asm volatile("cp.async.cg.shared.global [%0], [%1], 16;" :: "r"(saddr), "l"(g));
}
__device__ __forceinline__ void cp_commit() {
    asm volatile("cp.async.commit_group;" ::: "memory");
}
template <int N>
__device__ __forceinline__ void cp_wait() {
    asm volatile("cp.async.wait_group %0;" :: "n"(N) : "memory");
}
__device__ __forceinline__ void ldm4(uint32_t* r, uint32_t addr) {
    asm volatile("ldmatrix.sync.aligned.m8n8.x4.shared.b16 {%0,%1,%2,%3}, [%4];"
        : "=r"(r[0]), "=r"(r[1]), "=r"(r[2]), "=r"(r[3]) : "r"(addr));
}
// mma.sync m16n8k16 row.col fp16 -> f32 (baseline PTX)
__device__ __forceinline__ void mma16816(float* d, const uint32_t* a, const uint32_t* b) {
    asm volatile(
        "mma.sync.aligned.m16n8k16.row.col.f32.f16.f16.f32 "
        "{%0,%1,%2,%3}, {%4,%5,%6,%7}, {%8,%9}, {%0,%1,%2,%3};"
        : "+f"(d[0]), "+f"(d[1]), "+f"(d[2]), "+f"(d[3])
        : "r"(a[0]), "r"(a[1]), "r"(a[2]), "r"(a[3]), "r"(b[0]), "r"(b[1]));
}
__device__ __forceinline__ float sigm(float x) {
    return __fdividef(1.0f, 1.0f + __expf(-x));
}
__device__ __forceinline__ float ftanh(float x) {
    return __fdividef(2.0f, 1.0f + __expf(-2.0f * x)) - 1.0f;
}

#define SWZ(o) ((o) ^ (((o) >> 3) & 0x70))

// ---------------- SMEM layout ----------------
// [0,512): bias (128 floats).
// Stage (24 KB): A(64x128B)=8K @0, B(128x128B)=16K @8192. Two stages.
// z scratch (64x132 f32 = 33792 B) overlays stage 1 + tail (last chunk c=16 uses stage 0).
#define A_TILE_B 8192
#define B_TILE_B 16384
#define STAGE_B 24576
#define SM_STG 512
#define SM_TOTAL (SM_STG + STAGE_B + 33792)   // 58880

__device__ __forceinline__ void grid_barrier(unsigned target) {
    __threadfence();
    __syncthreads();
    if (threadIdx.x == 0) {
        if (atomicAdd(&g_bar[0], 1u) == NBLK - 1u) {
            atomicExch(&g_bar[0], 0u);
            __threadfence();
            atomicExch(&g_bar[1], target);
        } else {
            while (((volatile unsigned*)g_bar)[1] < target) __nanosleep(64);
            __threadfence();
        }
    }
    __syncthreads();
}

__global__ __launch_bounds__(256, 2)
void lstm_persist(const float* __restrict__ Wd,
                  const float* __restrict__ bd,
                  float* __restrict__ out)
{
    extern __shared__ char smem[];
    const uint32_t sbase = smem_u32(smem);
    const int tid = threadIdx.x, wid = tid >> 5, lane = tid & 31;
    const int warp_m = wid >> 2;            // 0..1 -> rows warp_m*32
    const int warp_n = wid & 3;             // 0..3 -> cols warp_n*32
    const int m0 = blockIdx.x * 64;         // batch tile (M=64)
    const int n0 = blockIdx.y * 128;        // gate-interleaved column base (N=128)
    const int u0 = blockIdx.y * 32;
    const int flat = blockIdx.y * gridDim.x + blockIdx.x;

    if (tid < 128) ((float*)smem)[tid] = g_b2[n0 + tid];

    const __half* __restrict__ Bw = g_Wt + (size_t)n0 * KTOT;

    const int a_r  = warp_m * 32 + (lane & 15);
    const int a_cs = (lane >> 4) * 16;
    const int b_r  = warp_n * 32 + (lane & 7) + ((lane >> 4) << 3);
    const int b_cs = ((lane >> 3) & 1) * 16;

    unsigned lgen = 0;

    // W loader (weights are step-invariant)
    auto issueW = [&](int c, int st) {
        const uint32_t sb = sbase + SM_STG + st * STAGE_B + A_TILE_B;
        #pragma unroll
        for (int i = 0; i < 4; ++i) {
            const int idx = i * 256 + tid;
            const int row = idx >> 3, ch = idx & 7;
            const uint32_t so = SWZ(row * 128 + ch * 16);
            cp16(sb + so, Bw + (size_t)row * KTOT + c * KCHUNK + ch * 8);
        }
    };

    #pragma unroll 1
    for (int t = 0; t < NSTEPS; ++t) {
        const __half* hi = (t & 1) ? g_hB : g_hA;
        __half* ho       = (t & 1) ? g_hA : g_hB;
        const __half* xp;
        int xstride;
        if (t < TIN) { xp = g_in + (size_t)t * FDIM; xstride = TIN * FDIM; }
        else         { xp = g_xd; xstride = FDIM; }

        auto issueA = [&](int c, int st) {
            const __half* ap;
            int lda;
            if (c < 16) { ap = hi + (size_t)m0 * UNITS + c * KCHUNK; lda = UNITS; }
            else        { ap = xp + (size_t)m0 * xstride;            lda = xstride; }
            const uint32_t sb = sbase + SM_STG + st * STAGE_B;
            #pragma unroll
            for (int i = 0; i < 2; ++i) {
                const int idx = i * 256 + tid;
                const int row = idx >> 3, ch = idx & 7;
                const uint32_t so = SWZ(row * 128 + ch * 16);
                cp16(sb + so, ap + (size_t)row * lda + ch * 8);
            }
        };

        int c0;
        if (t == 0) { c0 = 16; issueA(16, 0); issueW(16, 0); cp_commit(); }
        else        { c0 = 0;  issueA(0, 0);  cp_commit(); }   // W0 pre-issued last step

        float acc[2][4][4];
        #pragma unroll
        for (int i = 0; i < 2; ++i)
            #pragma unroll
            for (int j = 0; j < 4; ++j)
                #pragma unroll
                for (int r = 0; r < 4; ++r) acc[i][j][r] = 0.f;

        #pragma unroll 1
        for (int c = c0; c < NCHUNK; ++c) {
            const int st = c & 1;
            cp_wait<0>();
            __syncthreads();
            if (c + 1 < NCHUNK) { issueA(c + 1, st ^ 1); issueW(c + 1, st ^ 1); cp_commit(); }

            const uint32_t sb = sbase + SM_STG + st * STAGE_B;
            #pragma unroll
            for (int k16 = 0; k16 < 4; ++k16) {
                const int kb = k16 * 32;
                uint32_t ah[2][4], bh[2][4];
                #pragma unroll
                for (int mf = 0; mf < 2; ++mf) {
                    const uint32_t so = SWZ((a_r + mf * 16) * 128 + kb + a_cs);
                    ldm4(ah[mf], sb + so);
                }
                #pragma unroll
                for (int p = 0; p < 2; ++p) {
                    const uint32_t so = SWZ((b_r + p * 16) * 128 + kb + b_cs);
                    ldm4(bh[p], sb + A_TILE_B + so);
                }
                #pragma unroll
                for (int mf = 0; mf < 2; ++mf)
                    #pragma unroll
                    for (int nf = 0; nf < 4; ++nf)
                        mma16816(acc[mf][nf], ah[mf], &bh[nf >> 1][(nf & 1) * 2]);
            }
        }

        // ---- epilogue: z scratch overlays stage 1 (last chunk c=16 computed from stage 0) ----
        float* zs = (float*)(smem + SM_STG + STAGE_B);
        __syncthreads();
        {
            const int gr = lane >> 2, gcn = (lane & 3) * 2;
            #pragma unroll
            for (int mf = 0; mf < 2; ++mf)
                #pragma unroll
                for (int nf = 0; nf < 4; ++nf) {
                    const int row = warp_m * 32 + mf * 16 + gr;
                    const int col = warp_n * 32 + nf * 8 + gcn;
                    *(float2*)&zs[row * 132 + col]       = make_float2(acc[mf][nf][0], acc[mf][nf][1]);
                    *(float2*)&zs[(row + 8) * 132 + col] = make_float2(acc[mf][nf][2], acc[mf][nf][3]);
                }
        }
        __syncthreads();
        {
            const int m  = tid >> 2;
            const int ub = (tid & 3) * 8;
            const float4* zrow  = (const float4*)&zs[m * 132];
            const float4* bias4 = (const float4*)smem;
            const size_t idx0 = (size_t)(m0 + m) * UNITS + u0 + ub;
            __align__(16) float cf[8], hfv[8];
            __align__(8) __half hh[8];
            if (t == 0) {
                #pragma unroll
                for (int j = 0; j < 8; ++j) cf[j] = 0.f;
            } else {
                *(float4*)&cf[0] = *(const float4*)(g_c + idx0);
                *(float4*)&cf[4] = *(const float4*)(g_c + idx0 + 4);
            }
            #pragma unroll
            for (int j = 0; j < 8; ++j) {
                const int ul = ub + j;
                const float4 z4 = zrow[ul];
                const float4 bb = bias4[ul];
                const float zi = z4.x + bb.x;
                const float zf = z4.y + bb.y;
                const float zg = z4.z + bb.z;
                const float zo = z4.w + bb.w;
                const float cn = sigm(zf) * cf[j] + sigm(zi) * ftanh(zg);
                cf[j] = cn;
                const float h = sigm(zo) * ftanh(cn);
                hfv[j] = h;
                hh[j] = __float2half(h);
            }
            *(float4*)(g_c + idx0)     = *(const float4*)&cf[0];
            *(float4*)(g_c + idx0 + 4) = *(const float4*)&cf[4];
            *(uint4*)(ho + idx0) = *(const uint4*)&hh[0];
            if (t >= TIN - 1) {   // fp32 h needed only by the dense head
                *(float4*)(g_hf32 + idx0)     = *(const float4*)&hfv[0];
                *(float4*)(g_hf32 + idx0 + 4) = *(const float4*)&hfv[4];
            }
        }

        if (t + 1 < NSTEPS) { issueW(0, 0); cp_commit(); }   // prefetch next step's W0 across the barrier
        grid_barrier(++lgen);

        if (t >= TIN - 1) {
            const int ds = t - (TIN - 1);
            if (flat < 64) {
                const int bg = flat >> 3;
                const int fg = flat & 7;
                const int bl_ = tid >> 2;
                const int f0 = fg * 8 + (tid & 3);
                const int b  = bg * 64 + bl_;
                const float4* hp = (const float4*)(g_hf32 + (size_t)b * UNITS);
                float a0 = 0.f, a1 = 0.f;
                #pragma unroll 4
                for (int kq = 0; kq < UNITS / 4; ++kq) {
                    const float4 hv = __ldcg(hp + kq);
                    const float* w = Wd + (size_t)kq * 4 * FDIM;
                    a0 = fmaf(hv.x, w[f0], a0);            a1 = fmaf(hv.x, w[f0 + 4], a1);
                    a0 = fmaf(hv.y, w[64 + f0], a0);       a1 = fmaf(hv.y, w[64 + f0 + 4], a1);
                    a0 = fmaf(hv.z, w[128 + f0], a0);      a1 = fmaf(hv.z, w[128 + f0 + 4], a1);
                    a0 = fmaf(hv.w, w[192 + f0], a0);      a1 = fmaf(hv.w, w[192 + f0 + 4], a1);
                }
                const float p0 = a0 + bd[f0];
                const float p1 = a1 + bd[f0 + 4];
                out[(size_t)b * (OUT_STEPS * FDIM) + (size_t)ds * FDIM + f0]     = p0;
                out[(size_t)b * (OUT_STEPS * FDIM) + (size_t)ds * FDIM + f0 + 4] = p1;
                g_xd[(size_t)b * FDIM + f0]     = __float2half(p0);
                g_xd[(size_t)b * FDIM + f0 + 4] = __float2half(p1);
            }
            if (t + 1 < NSTEPS) grid_barrier(++lgen);
        }
    }
}

// ---------------- preprocessing: coalesced tiled transpose to fp16 ----------------
__global__ __launch_bounds__(256)
void prep_weights(const float* __restrict__ Wk, const float* __restrict__ Wr,
                  const float* __restrict__ b) {
    __shared__ float tile[64][65];            // [n'_loc][k_loc]
    const int k0 = blockIdx.x * 64;
    const int u0 = blockIdx.y * 16;
    const int r  = threadIdx.x >> 2;
    const int cq = threadIdx.x & 3;
    const int k  = k0 + r;
    #pragma unroll
    for (int g = 0; g < 4; ++g) {
        const int col = g * UNITS + u0 + cq * 4;
        float4 v;
        if (k < UNITS) v = *(const float4*)(Wr + (size_t)k * NGATE + col);
        else           v = *(const float4*)(Wk + (size_t)(k - UNITS) * NGATE + col);
        tile[(cq * 4 + 0) * 4 + g][r] = v.x;
        tile[(cq * 4 + 1) * 4 + g][r] = v.y;
        tile[(cq * 4 + 2) * 4 + g][r] = v.z;
        tile[(cq * 4 + 3) * 4 + g][r] = v.w;
    }
    if (blockIdx.x == 0 && blockIdx.y == 0)
        for (int i = threadIdx.x; i < NGATE; i += 256)
            g_b2[i] = b[(i & 3) * UNITS + (i >> 2)];
    __syncthreads();
    const int nl = threadIdx.x >> 2;
    const int kk = (threadIdx.x & 3) * 16;
    const size_t ng = (size_t)(blockIdx.y * 64 + nl);
    __align__(16) __half hb[16];
    #pragma unroll
    for (int j = 0; j < 16; ++j)
        hb[j] = __float2half(tile[nl][kk + j]);
    *(uint4*)(g_Wt + ng * KTOT + k0 + kk)     = *(const uint4*)&hb[0];
    *(uint4*)(g_Wt + ng * KTOT + k0 + kk + 8) = *(const uint4*)&hb[8];
}

__global__ void prep_inputs(const float* __restrict__ inp) {
    const size_t idx = (size_t)blockIdx.x * blockDim.x + threadIdx.x;
    if (idx < (size_t)BSZ * TIN * FDIM)
        g_in[idx] = __float2half(inp[idx]);
}

// ---------------- launch ----------------
extern "C" void kernel_launch(void* const* d_in, const int* in_sizes, int n_in,
                              void* d_out, int out_size)
{
    const float* inputs = (const float*)d_in[0];
    const float* Wk     = (const float*)d_in[1];
    const float* Wr     = (const float*)d_in[2];
    const float* bias   = (const float*)d_in[3];
    const float* Wd     = (const float*)d_in[4];
    const float* bd     = (const float*)d_in[5];
    float* out = (float*)d_out;

    static bool attr_done = false;
    if (!attr_done) {
        cudaFuncSetAttribute(lstm_persist, cudaFuncAttributeMaxDynamicSharedMemorySize, SM_TOTAL);
        attr_done = true;
    }

    void* bar_addr;
    cudaGetSymbolAddress(&bar_addr, g_bar);
    cudaMemsetAsync(bar_addr, 0, 2 * sizeof(unsigned));

    prep_weights<<<dim3(17, 64), 256>>>(Wk, Wr, bias);
    {
        const size_t ni = (size_t)BSZ * TIN * FDIM;
        prep_inputs<<<(unsigned)((ni + 255) / 256), 256>>>(inputs);
    }

    lstm_persist<<<dim3(BSZ / 64, NGATE / 128), 256, SM_TOTAL>>>(Wd, bd, out);
}